// round 9
// baseline (speedup 1.0000x reference)
#include <cuda_runtime.h>

// MixedActivation: cols with (col % 6) < 3 -> x*x ; else PReLU with slope
// prelu_a[(col % 6) - 3]. x is [1000000, 48] fp32, contiguous.
//
// R9: final policy cell — .cs (evict-first) LOADS + default STORES.
// Input lines are never reused -> evict-first keeps them out of L2, leaving
// maximum L2 capacity to buffer the dirty write stream for batched writeback.
// Geometry identical to best (R6): TPB=256 x UNROLL=3 float4 = 768/block,
// 12M float4 / 768 = 15625 blocks EXACTLY -> zero bounds checks.
//
// Measured context: MLP {3,4,8}, width {128b,256b}, policy {cs/cs, def/def}
// all pinned at 6.09-6.15 TB/s -> controller-level R/W-interleave ceiling.
//
// Phase logic: float4 index i covers cols 4i..4i+3; (4i) mod 6 depends only
// on r = i % 3: r=0 -> mods {0,1,2,3}, r=1 -> {4,5,0,1}, r=2 -> {2,3,4,5}.

#define UNROLL 3
#define TPB 256

__global__ void __launch_bounds__(TPB)
mixed_act_kernel(const float4* __restrict__ in,
                 const float* __restrict__ pa,
                 float4* __restrict__ out) {
    const int base = blockIdx.x * (TPB * UNROLL) + threadIdx.x;

    const float a0 = __ldg(pa + 0);
    const float a1 = __ldg(pa + 1);
    const float a2 = __ldg(pa + 2);

    // Front-batch all loads: 3 independent LDG.128 in flight per thread.
    float4 v[UNROLL];
#pragma unroll
    for (int k = 0; k < UNROLL; k++)
        v[k] = __ldcs(&in[base + k * TPB]);   // evict-first: input never reused

#pragma unroll
    for (int k = 0; k < UNROLL; k++) {
        const int i = base + k * TPB;
        int r = i % 3;       // phase of this float4 within the 6-col pattern
        int m0 = r * 4;      // (col % 12) of component 0; reduce mod 6 per c

        float x[4] = {v[k].x, v[k].y, v[k].z, v[k].w};
        float o[4];
#pragma unroll
        for (int c = 0; c < 4; c++) {
            int m = m0 + c;
            if (m >= 6) m -= 6;                   // m = col % 6 (0..5)
            float a = (m == 3) ? a0 : ((m == 4) ? a1 : a2);
            float sq = x[c] * x[c];
            float pr = fmaxf(x[c], 0.0f) + a * fminf(x[c], 0.0f);
            o[c] = (m < 3) ? sq : pr;             // predicated select
        }
        out[i] = make_float4(o[0], o[1], o[2], o[3]);  // default: L2-buffered
    }
}

extern "C" void kernel_launch(void* const* d_in, const int* in_sizes, int n_in,
                              void* d_out, int out_size) {
    const float* x  = (const float*)d_in[0];
    const float* pa = (const float*)d_in[1];
    float* out = (float*)d_out;

    int n4 = out_size / 4;                   // 12,000,000 float4s
    int blocks = n4 / (TPB * UNROLL);        // exactly 15625
    mixed_act_kernel<<<blocks, TPB>>>((const float4*)x, pa, (float4*)out);
}

// round 10
// speedup vs baseline: 1.0089x; 1.0089x over previous
#include <cuda_runtime.h>

// MixedActivation: cols with (col % 6) < 3 -> x*x ; else PReLU with slope
// prelu_a[(col % 6) - 3]. x is [1000000, 48] fp32, contiguous.
//
// FINAL (lock-in of R6, best measured: 53.66us kernel / 61.44us bench).
//
// Session findings: this kernel is pinned at the memory-controller ceiling
// (~6.1 TB/s = ~77% of HBM pin BW for a 1:1 read/write interleaved stream).
// Six configurations — MLP {3,4,8}, width {128b,256b}, cache policy
// {cs/cs, def/def, cs/def}, occupancy 52-80% — all measured within 0.7us of
// each other. Traffic (384 MB) is irreducible by the op contract, so this is
// the hardware floor.
//
// Geometry: TPB=256 x UNROLL=3 float4 = 768 float4/block;
// 12M float4 / 768 = 15625 blocks EXACTLY -> zero bounds checks/predicates.
// Phase logic: float4 index i covers cols 4i..4i+3; (4i) mod 6 depends only
// on r = i % 3: r=0 -> mods {0,1,2,3}, r=1 -> {4,5,0,1}, r=2 -> {2,3,4,5}.

#define UNROLL 3
#define TPB 256

__global__ void __launch_bounds__(TPB)
mixed_act_kernel(const float4* __restrict__ in,
                 const float* __restrict__ pa,
                 float4* __restrict__ out) {
    const int base = blockIdx.x * (TPB * UNROLL) + threadIdx.x;

    const float a0 = __ldg(pa + 0);
    const float a1 = __ldg(pa + 1);
    const float a2 = __ldg(pa + 2);

    // Front-batch all loads: 3 independent LDG.128 in flight per thread.
    float4 v[UNROLL];
#pragma unroll
    for (int k = 0; k < UNROLL; k++)
        v[k] = __ldcs(&in[base + k * TPB]);

#pragma unroll
    for (int k = 0; k < UNROLL; k++) {
        const int i = base + k * TPB;
        int r = i % 3;       // phase of this float4 within the 6-col pattern
        int m0 = r * 4;      // (col % 12) of component 0; reduce mod 6 per c

        float x[4] = {v[k].x, v[k].y, v[k].z, v[k].w};
        float o[4];
#pragma unroll
        for (int c = 0; c < 4; c++) {
            int m = m0 + c;
            if (m >= 6) m -= 6;                   // m = col % 6 (0..5)
            float a = (m == 3) ? a0 : ((m == 4) ? a1 : a2);
            float sq = x[c] * x[c];
            float pr = fmaxf(x[c], 0.0f) + a * fminf(x[c], 0.0f);
            o[c] = (m < 3) ? sq : pr;             // predicated select
        }
        __stcs(&out[i], make_float4(o[0], o[1], o[2], o[3]));
    }
}

extern "C" void kernel_launch(void* const* d_in, const int* in_sizes, int n_in,
                              void* d_out, int out_size) {
    const float* x  = (const float*)d_in[0];
    const float* pa = (const float*)d_in[1];
    float* out = (float*)d_out;

    int n4 = out_size / 4;                   // 12,000,000 float4s
    int blocks = n4 / (TPB * UNROLL);        // exactly 15625
    mixed_act_kernel<<<blocks, TPB>>>((const float4*)x, pa, (float4*)out);
}